// round 1
// baseline (speedup 1.0000x reference)
#include <cuda_runtime.h>
#include <math_constants.h>

#define NN 50000
#define NE 800000
#define DIM 96
#define NH 8
#define HD 12

// Scratch (static __device__ arrays; no allocation allowed)
__device__ float g_Q[NN * DIM];
__device__ float g_K[NN * DIM];
__device__ float g_V[NN * DIM];
__device__ float g_Z[NN * NH];
__device__ int   g_is64;

// ---------------------------------------------------------------------------
// Detect whether edge_index is int64 (little-endian high words == 0) or int32.
// Values are in [0, 50000), so for int64 every odd int32 word is 0.
// ---------------------------------------------------------------------------
__global__ void detect_idx_kernel(const int* __restrict__ eidx) {
    if (threadIdx.x == 0) {
        int acc = 0;
        for (int i = 0; i < 256; i++) acc |= eidx[2 * i + 1];
        g_is64 = (acc == 0) ? 1 : 0;
    }
}

// ---------------------------------------------------------------------------
// Zero the accumulators (d_out is poisoned by the harness; it is our wV acc)
// ---------------------------------------------------------------------------
__global__ void zero_kernel(float* __restrict__ out) {
    int i = blockIdx.x * blockDim.x + threadIdx.x;
    if (i < NN * DIM) out[i] = 0.0f;
    if (i < NN * NH)  g_Z[i] = 0.0f;
}

// ---------------------------------------------------------------------------
// QKV: out = x @ W + b for W in {Wq,Wk,Wv} selected by blockIdx.y.
// Block: 256 threads, tile 64 nodes x 96 cols, per-thread 4x6 register tile.
// smem: W (96x96) + b (96) + x tile (64x97 padded)
// ---------------------------------------------------------------------------
#define QKV_SMEM ((9216 + 96 + 64 * 97) * 4)

__global__ void qkv_kernel(const float* __restrict__ x,
                           const float* __restrict__ Wq, const float* __restrict__ bq,
                           const float* __restrict__ Wk, const float* __restrict__ bk,
                           const float* __restrict__ Wv, const float* __restrict__ bv) {
    extern __shared__ float sm[];
    float* Ws = sm;                  // 9216
    float* bs = sm + 9216;           // 96
    float* xs = sm + 9216 + 96;      // 64*97

    const float* W; const float* b; float* out;
    if (blockIdx.y == 0)      { W = Wq; b = bq; out = g_Q; }
    else if (blockIdx.y == 1) { W = Wk; b = bk; out = g_K; }
    else                      { W = Wv; b = bv; out = g_V; }

    int tid = threadIdx.x;
    for (int i = tid; i < 9216; i += 256) Ws[i] = W[i];
    if (tid < 96) bs[tid] = b[tid];

    int row0 = blockIdx.x * 64;
    for (int i = tid; i < 64 * 96; i += 256) {
        int r = i / 96, c = i - r * 96;
        int n = row0 + r;
        xs[r * 97 + c] = (n < NN) ? x[n * 96 + c] : 0.0f;
    }
    __syncthreads();

    int ty = tid >> 4, tx = tid & 15;
    int r0 = ty * 4, c0 = tx * 6;

    float acc[4][6];
#pragma unroll
    for (int i = 0; i < 4; i++)
#pragma unroll
        for (int j = 0; j < 6; j++) acc[i][j] = 0.0f;

#pragma unroll 4
    for (int k = 0; k < 96; k++) {
        float a[4], w[6];
#pragma unroll
        for (int i = 0; i < 4; i++) a[i] = xs[(r0 + i) * 97 + k];
#pragma unroll
        for (int j = 0; j < 6; j++) w[j] = Ws[k * 96 + c0 + j];
#pragma unroll
        for (int i = 0; i < 4; i++)
#pragma unroll
            for (int j = 0; j < 6; j++) acc[i][j] = fmaf(a[i], w[j], acc[i][j]);
    }

#pragma unroll
    for (int i = 0; i < 4; i++) {
        int n = row0 + r0 + i;
        if (n < NN) {
#pragma unroll
            for (int j = 0; j < 6; j++)
                out[n * 96 + c0 + j] = acc[i][j] + bs[c0 + j];
        }
    }
}

// ---------------------------------------------------------------------------
// Fused edge kernel. Tile = 64 edges, 256 threads.
// Phase A: E_tile[64,96] = edge_attr_tile @ We + be   (register-tiled GEMM)
// Phase B: 4 threads per edge, 2 heads each:
//          score_h = exp(clip(sum_d K[src]Q[dst]E / sqrt(12), -5, 5))
//          atomicAdd wV(dst) += V[src]*score ; atomicAdd Z(dst,h) += score
// ---------------------------------------------------------------------------
#define ETILE 64
#define EPAD 100
#define EDGE_SMEM ((9216 + 96 + ETILE * EPAD * 2) * 4)

__global__ void edge_kernel(const float* __restrict__ edge_attr,
                            const int* __restrict__ eidx,
                            const float* __restrict__ We, const float* __restrict__ be,
                            float* __restrict__ out) {
    extern __shared__ float sm[];
    float* Ws = sm;                          // 9216
    float* bs = sm + 9216;                   // 96
    float* ea = sm + 9216 + 96;              // 64*100
    float* Es = ea + ETILE * EPAD;           // 64*100

    int tid = threadIdx.x;
    for (int i = tid; i < 9216; i += 256) Ws[i] = We[i];
    if (tid < 96) bs[tid] = be[tid];

    int e0 = blockIdx.x * ETILE;
    for (int i = tid; i < ETILE * 96; i += 256) {
        int r = i / 96, c = i - r * 96;
        ea[r * EPAD + c] = edge_attr[(e0 + r) * 96 + c];
    }
    __syncthreads();

    // Phase A: GEMM into Es
    {
        int ty = tid >> 4, tx = tid & 15;
        int r0 = ty * 4, c0 = tx * 6;
        float acc[4][6];
#pragma unroll
        for (int i = 0; i < 4; i++)
#pragma unroll
            for (int j = 0; j < 6; j++) acc[i][j] = 0.0f;

#pragma unroll 4
        for (int k = 0; k < 96; k++) {
            float a[4], w[6];
#pragma unroll
            for (int i = 0; i < 4; i++) a[i] = ea[(r0 + i) * EPAD + k];
#pragma unroll
            for (int j = 0; j < 6; j++) w[j] = Ws[k * 96 + c0 + j];
#pragma unroll
            for (int i = 0; i < 4; i++)
#pragma unroll
                for (int j = 0; j < 6; j++) acc[i][j] = fmaf(a[i], w[j], acc[i][j]);
        }
#pragma unroll
        for (int i = 0; i < 4; i++)
#pragma unroll
            for (int j = 0; j < 6; j++)
                Es[(r0 + i) * EPAD + c0 + j] = acc[i][j] + bs[c0 + j];
    }
    __syncthreads();

    // Phase B: scoring + scatter. 4 threads per edge, 2 heads per thread.
    int li = tid >> 2;            // edge slot 0..63
    int p  = tid & 3;             // quarter -> heads 2p, 2p+1
    int e  = e0 + li;

    int src, dst;
    if (g_is64) {                 // int64 little-endian: take low words
        src = eidx[2 * e];
        dst = eidx[2 * NE + 2 * e];
    } else {
        src = eidx[e];
        dst = eidx[NE + e];
    }

    const float4* Kp = (const float4*)(g_K + src * 96);
    const float4* Qp = (const float4*)(g_Q + dst * 96);
    const float4* Vp = (const float4*)(g_V + src * 96);
    const float4* Ep = (const float4*)(Es + li * EPAD);

    const float inv_sqrt_d = 0.28867513459481287f;  // 1/sqrt(12)

#pragma unroll
    for (int hh = 0; hh < 2; hh++) {
        int h = 2 * p + hh;
        float s = 0.0f;
#pragma unroll
        for (int q = 0; q < 3; q++) {
            float4 kv = Kp[h * 3 + q];
            float4 qv = Qp[h * 3 + q];
            float4 ev = Ep[h * 3 + q];
            s += kv.x * qv.x * ev.x;
            s += kv.y * qv.y * ev.y;
            s += kv.z * qv.z * ev.z;
            s += kv.w * qv.w * ev.w;
        }
        s *= inv_sqrt_d;
        s = fminf(5.0f, fmaxf(-5.0f, s));
        s = __expf(s);

        atomicAdd(&g_Z[dst * NH + h], s);
        float* ob = out + dst * 96 + h * 12;
#pragma unroll
        for (int q = 0; q < 3; q++) {
            float4 vv = Vp[h * 3 + q];
            atomicAdd(&ob[q * 4 + 0], vv.x * s);
            atomicAdd(&ob[q * 4 + 1], vv.y * s);
            atomicAdd(&ob[q * 4 + 2], vv.z * s);
            atomicAdd(&ob[q * 4 + 3], vv.w * s);
        }
    }
}

// ---------------------------------------------------------------------------
// Finalize: out = wV / (Z + 1e-6)
// ---------------------------------------------------------------------------
__global__ void finalize_kernel(float* __restrict__ out) {
    int i = blockIdx.x * blockDim.x + threadIdx.x;
    if (i < NN * DIM) {
        int n = i / 96;
        int h = (i - n * 96) / 12;
        out[i] = out[i] / (g_Z[n * NH + h] + 1e-6f);
    }
}

// ---------------------------------------------------------------------------
extern "C" void kernel_launch(void* const* d_in, const int* in_sizes, int n_in,
                              void* d_out, int out_size) {
    const float* x    = (const float*)d_in[0];
    const int*   eidx = (const int*)  d_in[1];
    const float* ea   = (const float*)d_in[2];
    const float* Wq   = (const float*)d_in[3];
    const float* bq   = (const float*)d_in[4];
    const float* Wk   = (const float*)d_in[5];
    const float* bk   = (const float*)d_in[6];
    const float* We   = (const float*)d_in[7];
    const float* be   = (const float*)d_in[8];
    const float* Wv   = (const float*)d_in[9];
    const float* bv   = (const float*)d_in[10];
    float* out = (float*)d_out;

    cudaFuncSetAttribute(qkv_kernel,  cudaFuncAttributeMaxDynamicSharedMemorySize, QKV_SMEM);
    cudaFuncSetAttribute(edge_kernel, cudaFuncAttributeMaxDynamicSharedMemorySize, EDGE_SMEM);

    detect_idx_kernel<<<1, 32>>>(eidx);
    zero_kernel<<<(NN * DIM + 255) / 256, 256>>>(out);
    qkv_kernel<<<dim3((NN + 63) / 64, 3), 256, QKV_SMEM>>>(x, Wq, bq, Wk, bk, Wv, bv);
    edge_kernel<<<NE / ETILE, 256, EDGE_SMEM>>>(ea, eidx, We, be, out);
    finalize_kernel<<<(NN * DIM + 255) / 256, 256>>>(out);
}

// round 3
// speedup vs baseline: 1.5272x; 1.5272x over previous
#include <cuda_runtime.h>
#include <cuda_bf16.h>
#include <cstdint>

#define NN 50000
#define NE 800000
#define DIM 96
#define NH 8
#define HD 12

// ============================ scratch ======================================
__device__ float g_Q[NN * DIM];
__device__ float g_K[NN * DIM];
__device__ float g_V[NN * DIM];
__device__ float g_Z[NN * NH];
__device__ int   g_is64;
// W^T images: [4 weights][hi/lo][96 rows (out j) x 104 cols (in k)] bf16
// stored as uint4 for fast copy: 96*104*2B = 19968 B = 1248 uint4
__device__ uint4 g_WT[4][2][1248];

// ============================ smem layout ==================================
// A_hi [128][104] bf16 = 26624 B
// A_lo [128][104] bf16 = 26624 B
// B_hi [96][104]  bf16 = 19968 B
// B_lo [96][104]  bf16 = 19968 B
// E    [128][100] f32  = 51200 B  (overlaps A_hi+A_lo after GEMM)
#define SM_AH 0
#define SM_AL 26624
#define SM_BH 53248
#define SM_BL 73216
#define SM_E  0
#define SMEM_BYTES 93184
#define ASTRIDE 104
#define ESTRIDE 100

// ============================ helpers ======================================
__device__ __forceinline__ void mma_bf16(float c[4], uint32_t a0, uint32_t a1,
                                         uint32_t a2, uint32_t a3,
                                         uint32_t b0, uint32_t b1) {
    asm volatile(
        "mma.sync.aligned.m16n8k16.row.col.f32.bf16.bf16.f32 "
        "{%0,%1,%2,%3}, {%4,%5,%6,%7}, {%8,%9}, {%0,%1,%2,%3};"
        : "+f"(c[0]), "+f"(c[1]), "+f"(c[2]), "+f"(c[3])
        : "r"(a0), "r"(a1), "r"(a2), "r"(a3), "r"(b0), "r"(b1));
}

__device__ __forceinline__ void split_pack(float4 v, uint32_t& hi0, uint32_t& hi1,
                                           uint32_t& lo0, uint32_t& lo1) {
    __nv_bfloat16 h0 = __float2bfloat16(v.x), h1 = __float2bfloat16(v.y);
    __nv_bfloat16 h2 = __float2bfloat16(v.z), h3 = __float2bfloat16(v.w);
    __nv_bfloat16 l0 = __float2bfloat16(v.x - __bfloat162float(h0));
    __nv_bfloat16 l1 = __float2bfloat16(v.y - __bfloat162float(h1));
    __nv_bfloat16 l2 = __float2bfloat16(v.z - __bfloat162float(h2));
    __nv_bfloat16 l3 = __float2bfloat16(v.w - __bfloat162float(h3));
    hi0 = (uint32_t)__bfloat16_as_ushort(h0) | ((uint32_t)__bfloat16_as_ushort(h1) << 16);
    hi1 = (uint32_t)__bfloat16_as_ushort(h2) | ((uint32_t)__bfloat16_as_ushort(h3) << 16);
    lo0 = (uint32_t)__bfloat16_as_ushort(l0) | ((uint32_t)__bfloat16_as_ushort(l1) << 16);
    lo1 = (uint32_t)__bfloat16_as_ushort(l2) | ((uint32_t)__bfloat16_as_ushort(l3) << 16);
}

// Warp GEMM: C[16][96] = A_tile[rows r0..r0+15][0..95] @ Bt^T, 3-pass bf16.
// acc layout: acc[n][0..3] = fragment for n-block n (cols n*8..n*8+7).
__device__ __forceinline__ void warp_gemm(char* smem, int r0, int lane, float acc[12][4]) {
#pragma unroll
    for (int n = 0; n < 12; n++)
#pragma unroll
        for (int i = 0; i < 4; i++) acc[n][i] = 0.f;

    const int arow = r0 + (lane >> 2);
    const int kcol = (lane & 3) * 2;
    const int brow = lane >> 2;

#pragma unroll
    for (int p = 0; p < 3; p++) {
        const __nv_bfloat16* A = (const __nv_bfloat16*)(smem + (p == 2 ? SM_AL : SM_AH));
        const __nv_bfloat16* B = (const __nv_bfloat16*)(smem + (p == 1 ? SM_BL : SM_BH));
#pragma unroll
        for (int ks = 0; ks < 6; ks++) {
            int k0 = ks * 16;
            uint32_t a0 = *(const uint32_t*)(A + (size_t)arow * ASTRIDE + k0 + kcol);
            uint32_t a1 = *(const uint32_t*)(A + (size_t)(arow + 8) * ASTRIDE + k0 + kcol);
            uint32_t a2 = *(const uint32_t*)(A + (size_t)arow * ASTRIDE + k0 + kcol + 8);
            uint32_t a3 = *(const uint32_t*)(A + (size_t)(arow + 8) * ASTRIDE + k0 + kcol + 8);
#pragma unroll
            for (int n = 0; n < 12; n++) {
                const __nv_bfloat16* bp = B + (size_t)(n * 8 + brow) * ASTRIDE + k0 + kcol;
                uint32_t b0 = *(const uint32_t*)(bp);
                uint32_t b1 = *(const uint32_t*)(bp + 8);
                mma_bf16(acc[n], a0, a1, a2, a3, b0, b1);
            }
        }
    }
}

// =========================== small kernels =================================
__global__ void detect_idx_kernel(const int* __restrict__ eidx) {
    if (threadIdx.x == 0) {
        int acc = 0;
        for (int i = 0; i < 256; i++) acc |= eidx[2 * i + 1];
        g_is64 = (acc == 0) ? 1 : 0;
    }
}

__global__ void zero_kernel(float* __restrict__ out) {
    int i = blockIdx.x * blockDim.x + threadIdx.x;
    if (i < NN * DIM) out[i] = 0.0f;
    if (i < NN * NH)  g_Z[i] = 0.0f;
}

// Build W^T hi/lo bf16 images. Block b -> weight b (0=Wq,1=Wk,2=Wv,3=We).
__global__ void prep_weights_kernel(const float* __restrict__ Wq, const float* __restrict__ Wk,
                                    const float* __restrict__ Wv, const float* __restrict__ We) {
    const float* W = (blockIdx.x == 0) ? Wq : (blockIdx.x == 1) ? Wk
                   : (blockIdx.x == 2) ? Wv : We;
    unsigned short* hi = (unsigned short*)g_WT[blockIdx.x][0];
    unsigned short* lo = (unsigned short*)g_WT[blockIdx.x][1];
    for (int i = threadIdx.x; i < 96 * 104; i += blockDim.x) {   // zero pad region
        hi[i] = 0; lo[i] = 0;
    }
    __syncthreads();
    for (int i = threadIdx.x; i < 96 * 96; i += blockDim.x) {
        int k = i / 96, j = i - k * 96;          // W[k][j] -> WT[j][k]
        float v = W[i];
        __nv_bfloat16 h = __float2bfloat16(v);
        __nv_bfloat16 l = __float2bfloat16(v - __bfloat162float(h));
        hi[j * ASTRIDE + k] = __bfloat16_as_ushort(h);
        lo[j * ASTRIDE + k] = __bfloat16_as_ushort(l);
    }
}

// ============================ QKV kernel ===================================
// grid (391, 3), block 256. Tile 128 nodes x 96 out-cols.
__global__ void __launch_bounds__(256, 2)
qkv_kernel(const float* __restrict__ x,
           const float* __restrict__ bq, const float* __restrict__ bk,
           const float* __restrict__ bv) {
    extern __shared__ __align__(16) char smem[];
    int tid = threadIdx.x, wid = tid >> 5, lane = tid & 31;
    int w = blockIdx.y;
    const float* bias = (w == 0) ? bq : (w == 1) ? bk : bv;
    float* out = (w == 0) ? g_Q : (w == 1) ? g_K : g_V;

    // copy W^T images
    {
        const uint4* sh = g_WT[w][0];
        const uint4* sl = g_WT[w][1];
        uint4* dh = (uint4*)(smem + SM_BH);
        uint4* dl = (uint4*)(smem + SM_BL);
        for (int i = tid; i < 1248; i += 256) { dh[i] = sh[i]; dl[i] = sl[i]; }
    }
    // stage x tile -> bf16 hi/lo
    int row0 = blockIdx.x * 128;
    __nv_bfloat16* Ah = (__nv_bfloat16*)(smem + SM_AH);
    __nv_bfloat16* Al = (__nv_bfloat16*)(smem + SM_AL);
    for (int g = tid; g < 3072; g += 256) {          // 128 rows x 24 quads
        int r = g / 24, c = (g - r * 24) * 4;
        int n = row0 + r;
        float4 v = (n < NN) ? *(const float4*)(x + (size_t)n * 96 + c)
                            : make_float4(0.f, 0.f, 0.f, 0.f);
        uint32_t h0, h1, l0, l1;
        split_pack(v, h0, h1, l0, l1);
        *(uint2*)(Ah + (size_t)r * ASTRIDE + c) = make_uint2(h0, h1);
        *(uint2*)(Al + (size_t)r * ASTRIDE + c) = make_uint2(l0, l1);
    }
    __syncthreads();

    float acc[12][4];
    warp_gemm(smem, wid * 16, lane, acc);

    // epilogue: fragments -> global (+bias)
    int rlo = row0 + wid * 16 + (lane >> 2);
    int cb = (lane & 3) * 2;
#pragma unroll
    for (int n = 0; n < 12; n++) {
        int col = n * 8 + cb;
        float b0 = __ldg(bias + col), b1 = __ldg(bias + col + 1);
        if (rlo < NN)
            *(float2*)(out + (size_t)rlo * 96 + col) = make_float2(acc[n][0] + b0, acc[n][1] + b1);
        if (rlo + 8 < NN)
            *(float2*)(out + (size_t)(rlo + 8) * 96 + col) = make_float2(acc[n][2] + b0, acc[n][3] + b1);
    }
}

// ============================ Edge kernel ==================================
// grid 6250, block 256. 128 edges/tile. Fused E-GEMM + scoring + scatter.
__global__ void __launch_bounds__(256, 2)
edge_kernel(const float* __restrict__ edge_attr, const int* __restrict__ eidx,
            const float* __restrict__ be, float* __restrict__ out) {
    extern __shared__ __align__(16) char smem[];
    int tid = threadIdx.x, wid = tid >> 5, lane = tid & 31;

    {
        const uint4* sh = g_WT[3][0];
        const uint4* sl = g_WT[3][1];
        uint4* dh = (uint4*)(smem + SM_BH);
        uint4* dl = (uint4*)(smem + SM_BL);
        for (int i = tid; i < 1248; i += 256) { dh[i] = sh[i]; dl[i] = sl[i]; }
    }
    int e0 = blockIdx.x * 128;
    __nv_bfloat16* Ah = (__nv_bfloat16*)(smem + SM_AH);
    __nv_bfloat16* Al = (__nv_bfloat16*)(smem + SM_AL);
    for (int g = tid; g < 3072; g += 256) {
        int r = g / 24, c = (g - r * 24) * 4;
        float4 v = *(const float4*)(edge_attr + (size_t)(e0 + r) * 96 + c);
        uint32_t h0, h1, l0, l1;
        split_pack(v, h0, h1, l0, l1);
        *(uint2*)(Ah + (size_t)r * ASTRIDE + c) = make_uint2(h0, h1);
        *(uint2*)(Al + (size_t)r * ASTRIDE + c) = make_uint2(l0, l1);
    }
    __syncthreads();

    float acc[12][4];
    warp_gemm(smem, wid * 16, lane, acc);
    __syncthreads();   // all warps done reading A region before E overwrites it

    // write E (+bias) into smem
    float* E = (float*)(smem + SM_E);
    {
        int rlo = wid * 16 + (lane >> 2);
        int cb = (lane & 3) * 2;
#pragma unroll
        for (int n = 0; n < 12; n++) {
            int col = n * 8 + cb;
            float b0 = __ldg(be + col), b1 = __ldg(be + col + 1);
            *(float2*)(E + (size_t)rlo * ESTRIDE + col) =
                make_float2(acc[n][0] + b0, acc[n][1] + b1);
            *(float2*)(E + (size_t)(rlo + 8) * ESTRIDE + col) =
                make_float2(acc[n][2] + b0, acc[n][3] + b1);
        }
    }
    __syncthreads();

    // Phase B: 2 threads per edge; thread handles 4 heads (48 cols)
    int el = tid >> 1;
    int half = tid & 1;
    int e = e0 + el;
    int src, dst;
    if (g_is64) { src = __ldg(eidx + 2 * (size_t)e); dst = __ldg(eidx + 2 * (size_t)NE + 2 * (size_t)e); }
    else        { src = __ldg(eidx + e);             dst = __ldg(eidx + NE + e); }

    float ev[48];
    {
        const float4* Ep = (const float4*)(E + (size_t)el * ESTRIDE + half * 48);
#pragma unroll
        for (int i = 0; i < 12; i++) {
            float4 t = Ep[i];
            ev[i * 4 + 0] = t.x; ev[i * 4 + 1] = t.y; ev[i * 4 + 2] = t.z; ev[i * 4 + 3] = t.w;
        }
    }

    int hb = half * 4;
    const float4* Kp = (const float4*)(g_K + (size_t)src * 96 + hb * 12);
    const float4* Qp = (const float4*)(g_Q + (size_t)dst * 96 + hb * 12);
    const float4* Vp = (const float4*)(g_V + (size_t)src * 96 + hb * 12);
    float* ob = out + (size_t)dst * 96 + hb * 12;
    const float inv_sqrt_d = 0.28867513459481287f;

#pragma unroll
    for (int h = 0; h < 4; h++) {
        float s = 0.f;
#pragma unroll
        for (int j = 0; j < 3; j++) {
            float4 kv = __ldg(Kp + h * 3 + j);
            float4 qv = __ldg(Qp + h * 3 + j);
            s += (kv.x * qv.x) * ev[h * 12 + j * 4 + 0];
            s += (kv.y * qv.y) * ev[h * 12 + j * 4 + 1];
            s += (kv.z * qv.z) * ev[h * 12 + j * 4 + 2];
            s += (kv.w * qv.w) * ev[h * 12 + j * 4 + 3];
        }
        s *= inv_sqrt_d;
        s = fminf(5.0f, fmaxf(-5.0f, s));
        s = __expf(s);
        atomicAdd(&g_Z[(size_t)dst * NH + hb + h], s);
#pragma unroll
        for (int j = 0; j < 3; j++) {
            float4 vv = __ldg(Vp + h * 3 + j);
            asm volatile("red.global.add.v4.f32 [%0], {%1, %2, %3, %4};"
                         :: "l"(ob + h * 12 + j * 4),
                            "f"(vv.x * s), "f"(vv.y * s), "f"(vv.z * s), "f"(vv.w * s)
                         : "memory");
        }
    }
}

// ============================ finalize =====================================
__global__ void finalize_kernel(float* __restrict__ out) {
    int i = blockIdx.x * blockDim.x + threadIdx.x;
    if (i < NN * DIM) {
        int n = i / 96;
        int h = (i - n * 96) / 12;
        out[i] = out[i] / (g_Z[(size_t)n * NH + h] + 1e-6f);
    }
}

// ============================ launch =======================================
extern "C" void kernel_launch(void* const* d_in, const int* in_sizes, int n_in,
                              void* d_out, int out_size) {
    const float* x    = (const float*)d_in[0];
    const int*   eidx = (const int*)  d_in[1];
    const float* ea   = (const float*)d_in[2];
    const float* Wq   = (const float*)d_in[3];
    const float* bq   = (const float*)d_in[4];
    const float* Wk   = (const float*)d_in[5];
    const float* bk   = (const float*)d_in[6];
    const float* We   = (const float*)d_in[7];
    const float* be   = (const float*)d_in[8];
    const float* Wv   = (const float*)d_in[9];
    const float* bv   = (const float*)d_in[10];
    float* out = (float*)d_out;

    cudaFuncSetAttribute(qkv_kernel,  cudaFuncAttributeMaxDynamicSharedMemorySize, SMEM_BYTES);
    cudaFuncSetAttribute(edge_kernel, cudaFuncAttributeMaxDynamicSharedMemorySize, SMEM_BYTES);

    detect_idx_kernel<<<1, 32>>>(eidx);
    zero_kernel<<<(NN * DIM + 255) / 256, 256>>>(out);
    prep_weights_kernel<<<4, 256>>>(Wq, Wk, Wv, We);
    qkv_kernel<<<dim3((NN + 127) / 128, 3), 256, SMEM_BYTES>>>(x, bq, bk, bv);
    edge_kernel<<<NE / 128, 256, SMEM_BYTES>>>(ea, eidx, be, out);
    finalize_kernel<<<(NN * DIM + 255) / 256, 256>>>(out);
}

// round 4
// speedup vs baseline: 2.0703x; 1.3556x over previous
#include <cuda_runtime.h>
#include <cuda_bf16.h>
#include <cstdint>

#define NN 50000
#define NE 800000
#define DIM 96
#define NH 8
#define HD 12

// ============================ scratch ======================================
__device__ float g_Q[NN * DIM];
__device__ float g_K[NN * DIM];
__device__ float g_V[NN * DIM];
__device__ int   g_is64;
// W^T images: [4 weights][hi/lo][96 rows (out j) x 104 cols (in k)] bf16
__device__ uint4 g_WT[4][2][1248];
// CSR + scores
__device__ int   g_deg[NN];
__device__ int   g_rowptr[NN + 1];
__device__ int   g_off[NN];
__device__ int   g_perm[NE];
__device__ float g_score[NE * NH];

// ============================ smem layout ==================================
// A [128][100] fp32 = 51200 B  (reused as E [128][100] fp32 in score kernel)
// B_hi [96][104] bf16 = 19968 B ; B_lo same
#define SM_A  0
#define SM_BH 51200
#define SM_BL 71168
#define SMEM_BYTES 91136
#define ASTR 100   // fp32 stride (floats)
#define BSTR 104   // bf16 stride (elements)

// ============================ helpers ======================================
__device__ __forceinline__ uint32_t smem_u32(const void* p) {
    uint32_t a;
    asm("{ .reg .u64 t; cvta.to.shared.u64 t, %1; cvt.u32.u64 %0, t; }" : "=r"(a) : "l"(p));
    return a;
}
__device__ __forceinline__ void cp16(uint32_t s, const void* g) {
    asm volatile("cp.async.ca.shared.global [%0], [%1], 16;" :: "r"(s), "l"(g));
}
#define CP_COMMIT_WAIT() do { \
    asm volatile("cp.async.commit_group;"); \
    asm volatile("cp.async.wait_group 0;" ::: "memory"); } while (0)

__device__ __forceinline__ void mma_bf16(float c[4], uint32_t a0, uint32_t a1,
                                         uint32_t a2, uint32_t a3,
                                         uint32_t b0, uint32_t b1) {
    asm volatile(
        "mma.sync.aligned.m16n8k16.row.col.f32.bf16.bf16.f32 "
        "{%0,%1,%2,%3}, {%4,%5,%6,%7}, {%8,%9}, {%0,%1,%2,%3};"
        : "+f"(c[0]), "+f"(c[1]), "+f"(c[2]), "+f"(c[3])
        : "r"(a0), "r"(a1), "r"(a2), "r"(a3), "r"(b0), "r"(b1));
}

__device__ __forceinline__ void split2(float2 f, uint32_t& hi, uint32_t& lo) {
    __nv_bfloat16 h0 = __float2bfloat16(f.x), h1 = __float2bfloat16(f.y);
    __nv_bfloat16 l0 = __float2bfloat16(f.x - __bfloat162float(h0));
    __nv_bfloat16 l1 = __float2bfloat16(f.y - __bfloat162float(h1));
    hi = (uint32_t)__bfloat16_as_ushort(h0) | ((uint32_t)__bfloat16_as_ushort(h1) << 16);
    lo = (uint32_t)__bfloat16_as_ushort(l0) | ((uint32_t)__bfloat16_as_ushort(l1) << 16);
}

// Warp GEMM: C[16][96] = A[r0..r0+15][0..95] (fp32 smem) @ W^T, 3-term bf16 comp.
__device__ __forceinline__ void warp_gemm(const float* As, const char* smem,
                                          int r0, int lane, float acc[12][4]) {
#pragma unroll
    for (int n = 0; n < 12; n++)
#pragma unroll
        for (int i = 0; i < 4; i++) acc[n][i] = 0.f;

    const int ar = r0 + (lane >> 2);
    const int kc = (lane & 3) * 2;
    const int br = lane >> 2;
    const __nv_bfloat16* Bh = (const __nv_bfloat16*)(smem + SM_BH);
    const __nv_bfloat16* Bl = (const __nv_bfloat16*)(smem + SM_BL);

#pragma unroll
    for (int ks = 0; ks < 6; ks++) {
        int k0 = ks * 16;
        float2 f0 = *(const float2*)(As + (size_t)ar * ASTR + k0 + kc);
        float2 f1 = *(const float2*)(As + (size_t)(ar + 8) * ASTR + k0 + kc);
        float2 f2 = *(const float2*)(As + (size_t)ar * ASTR + k0 + kc + 8);
        float2 f3 = *(const float2*)(As + (size_t)(ar + 8) * ASTR + k0 + kc + 8);
        uint32_t ah0, ah1, ah2, ah3, al0, al1, al2, al3;
        split2(f0, ah0, al0); split2(f1, ah1, al1);
        split2(f2, ah2, al2); split2(f3, ah3, al3);
#pragma unroll
        for (int n = 0; n < 12; n++) {
            const __nv_bfloat16* bh = Bh + (size_t)(n * 8 + br) * BSTR + k0 + kc;
            const __nv_bfloat16* bl = Bl + (size_t)(n * 8 + br) * BSTR + k0 + kc;
            uint32_t b0 = *(const uint32_t*)(bh);
            uint32_t b1 = *(const uint32_t*)(bh + 8);
            uint32_t c0 = *(const uint32_t*)(bl);
            uint32_t c1 = *(const uint32_t*)(bl + 8);
            mma_bf16(acc[n], ah0, ah1, ah2, ah3, b0, b1);
            mma_bf16(acc[n], al0, al1, al2, al3, b0, b1);
            mma_bf16(acc[n], ah0, ah1, ah2, ah3, c0, c1);
        }
    }
}

// =========================== small kernels =================================
__global__ void detect_idx_kernel(const int* __restrict__ eidx) {
    if (threadIdx.x == 0) {
        int acc = 0;
        for (int i = 0; i < 256; i++) acc |= eidx[2 * i + 1];
        g_is64 = (acc == 0) ? 1 : 0;
    }
}

__global__ void zero_deg_kernel() {
    int i = blockIdx.x * blockDim.x + threadIdx.x;
    if (i < NN) g_deg[i] = 0;
}

__global__ void prep_weights_kernel(const float* __restrict__ Wq, const float* __restrict__ Wk,
                                    const float* __restrict__ Wv, const float* __restrict__ We) {
    const float* W = (blockIdx.x == 0) ? Wq : (blockIdx.x == 1) ? Wk
                   : (blockIdx.x == 2) ? Wv : We;
    unsigned short* hi = (unsigned short*)g_WT[blockIdx.x][0];
    unsigned short* lo = (unsigned short*)g_WT[blockIdx.x][1];
    for (int i = threadIdx.x; i < 96 * BSTR; i += blockDim.x) { hi[i] = 0; lo[i] = 0; }
    __syncthreads();
    for (int i = threadIdx.x; i < 96 * 96; i += blockDim.x) {
        int k = i / 96, j = i - k * 96;          // W[k][j] -> WT[j][k]
        float v = W[i];
        __nv_bfloat16 h = __float2bfloat16(v);
        __nv_bfloat16 l = __float2bfloat16(v - __bfloat162float(h));
        hi[j * BSTR + k] = __bfloat16_as_ushort(h);
        lo[j * BSTR + k] = __bfloat16_as_ushort(l);
    }
}

__global__ void hist_kernel(const int* __restrict__ eidx) {
    int e = blockIdx.x * blockDim.x + threadIdx.x;
    if (e < NE) {
        int dst = g_is64 ? __ldg(eidx + 2 * (NE + e)) : __ldg(eidx + NE + e);
        atomicAdd(&g_deg[dst], 1);
    }
}

// single-block exclusive scan over g_deg -> g_rowptr, g_off
__global__ void scan_kernel() {
    const int PER = 49;                         // 1024*49 = 50176 >= 50000
    int tid = threadIdx.x;
    int base = tid * PER;
    int sum = 0;
    for (int i = 0; i < PER; i++) {
        int idx = base + i;
        if (idx < NN) sum += g_deg[idx];
    }
    __shared__ int wsum[32];
    int lane = tid & 31, w = tid >> 5;
    int v = sum;
#pragma unroll
    for (int o = 1; o < 32; o <<= 1) {
        int t = __shfl_up_sync(0xFFFFFFFFu, v, o);
        if (lane >= o) v += t;
    }
    if (lane == 31) wsum[w] = v;
    __syncthreads();
    if (w == 0) {
        int s = wsum[lane];
#pragma unroll
        for (int o = 1; o < 32; o <<= 1) {
            int t = __shfl_up_sync(0xFFFFFFFFu, s, o);
            if (lane >= o) s += t;
        }
        wsum[lane] = s;
    }
    __syncthreads();
    int excl = v - sum + (w > 0 ? wsum[w - 1] : 0);
    int run = excl;
    for (int i = 0; i < PER; i++) {
        int idx = base + i;
        if (idx < NN) {
            g_rowptr[idx] = run;
            g_off[idx] = run;
            run += g_deg[idx];
        }
    }
    if (tid == 1023) g_rowptr[NN] = NE;
}

__global__ void scatter_kernel(const int* __restrict__ eidx) {
    int e = blockIdx.x * blockDim.x + threadIdx.x;
    if (e < NE) {
        int dst = g_is64 ? __ldg(eidx + 2 * (NE + e)) : __ldg(eidx + NE + e);
        int pos = atomicAdd(&g_off[dst], 1);
        g_perm[pos] = e;
    }
}

// ============================ QKV kernel ===================================
__global__ void __launch_bounds__(256, 2)
qkv_kernel(const float* __restrict__ x,
           const float* __restrict__ bq, const float* __restrict__ bk,
           const float* __restrict__ bv) {
    extern __shared__ __align__(16) char smem[];
    uint32_t sb = smem_u32(smem);
    int tid = threadIdx.x, wid = tid >> 5, lane = tid & 31;
    int w = blockIdx.y;
    const float* bias = (w == 0) ? bq : (w == 1) ? bk : bv;
    float* out = (w == 0) ? g_Q : (w == 1) ? g_K : g_V;

    // W images via cp.async
    {
        const uint4* sh = g_WT[w][0];
        const uint4* sl = g_WT[w][1];
        for (int i = tid; i < 1248; i += 256) {
            cp16(sb + SM_BH + i * 16, sh + i);
            cp16(sb + SM_BL + i * 16, sl + i);
        }
    }
    // A tile fp32 via cp.async (rows guarded)
    int row0 = blockIdx.x * 128;
    for (int i = tid; i < 3072; i += 256) {     // 128 rows x 24 quads
        int r = i / 24, q = i - r * 24;
        int n = row0 + r;
        if (n < NN)
            cp16(sb + SM_A + (uint32_t)(r * ASTR + q * 4) * 4, x + (size_t)n * 96 + q * 4);
    }
    CP_COMMIT_WAIT();
    __syncthreads();

    float acc[12][4];
    warp_gemm((const float*)smem, smem, wid * 16, lane, acc);

    int rl = row0 + wid * 16 + (lane >> 2);
    int cb = (lane & 3) * 2;
#pragma unroll
    for (int n = 0; n < 12; n++) {
        int col = n * 8 + cb;
        float b0 = __ldg(bias + col), b1 = __ldg(bias + col + 1);
        if (rl < NN)
            *(float2*)(out + (size_t)rl * 96 + col) = make_float2(acc[n][0] + b0, acc[n][1] + b1);
        if (rl + 8 < NN)
            *(float2*)(out + (size_t)(rl + 8) * 96 + col) = make_float2(acc[n][2] + b0, acc[n][3] + b1);
    }
}

// ============================ Score kernel =================================
// grid 6250. E-GEMM -> smem E -> per-edge scores -> g_score. No atomics.
__global__ void __launch_bounds__(256, 2)
score_kernel(const float* __restrict__ edge_attr, const int* __restrict__ eidx,
             const float* __restrict__ be) {
    extern __shared__ __align__(16) char smem[];
    uint32_t sb = smem_u32(smem);
    int tid = threadIdx.x, wid = tid >> 5, lane = tid & 31;

    {
        const uint4* sh = g_WT[3][0];
        const uint4* sl = g_WT[3][1];
        for (int i = tid; i < 1248; i += 256) {
            cp16(sb + SM_BH + i * 16, sh + i);
            cp16(sb + SM_BL + i * 16, sl + i);
        }
    }
    int e0 = blockIdx.x * 128;
    for (int i = tid; i < 3072; i += 256) {
        int r = i / 24, q = i - r * 24;
        cp16(sb + SM_A + (uint32_t)(r * ASTR + q * 4) * 4,
             edge_attr + (size_t)(e0 + r) * 96 + q * 4);
    }
    CP_COMMIT_WAIT();
    __syncthreads();

    float acc[12][4];
    warp_gemm((const float*)smem, smem, wid * 16, lane, acc);
    __syncthreads();   // all warps done reading A before E overwrites it

    float* E = (float*)smem;
    {
        int rl = wid * 16 + (lane >> 2);
        int cb = (lane & 3) * 2;
#pragma unroll
        for (int n = 0; n < 12; n++) {
            int col = n * 8 + cb;
            float b0 = __ldg(be + col), b1 = __ldg(be + col + 1);
            *(float2*)(E + (size_t)rl * ASTR + col) = make_float2(acc[n][0] + b0, acc[n][1] + b1);
            *(float2*)(E + (size_t)(rl + 8) * ASTR + col) = make_float2(acc[n][2] + b0, acc[n][3] + b1);
        }
    }
    __syncthreads();

    // 2 threads/edge, 4 heads each
    int el = tid >> 1;
    int half = tid & 1;
    int e = e0 + el;
    int src, dst;
    if (g_is64) { src = __ldg(eidx + 2 * e); dst = __ldg(eidx + 2 * (NE + e)); }
    else        { src = __ldg(eidx + e);     dst = __ldg(eidx + NE + e); }

    float ev[48];
    {
        const float4* Ep = (const float4*)(E + (size_t)el * ASTR + half * 48);
#pragma unroll
        for (int i = 0; i < 12; i++) {
            float4 t = Ep[i];
            ev[i * 4 + 0] = t.x; ev[i * 4 + 1] = t.y; ev[i * 4 + 2] = t.z; ev[i * 4 + 3] = t.w;
        }
    }
    int hb = half * 4;
    const float4* Kp = (const float4*)(g_K + (size_t)src * 96 + hb * 12);
    const float4* Qp = (const float4*)(g_Q + (size_t)dst * 96 + hb * 12);
    const float inv_sqrt_d = 0.28867513459481287f;

    float sc[4];
#pragma unroll
    for (int h = 0; h < 4; h++) {
        float s = 0.f;
#pragma unroll
        for (int j = 0; j < 3; j++) {
            float4 kv = __ldg(Kp + h * 3 + j);
            float4 qv = __ldg(Qp + h * 3 + j);
            s += (kv.x * qv.x) * ev[h * 12 + j * 4 + 0];
            s += (kv.y * qv.y) * ev[h * 12 + j * 4 + 1];
            s += (kv.z * qv.z) * ev[h * 12 + j * 4 + 2];
            s += (kv.w * qv.w) * ev[h * 12 + j * 4 + 3];
        }
        s *= inv_sqrt_d;
        s = fminf(5.0f, fmaxf(-5.0f, s));
        sc[h] = __expf(s);
    }
    *(float4*)(g_score + (size_t)e * 8 + hb) = make_float4(sc[0], sc[1], sc[2], sc[3]);
}

// ============================ Aggregate ====================================
// One warp per dst node. Thread t owns cols 3t..3t+2 (head = t>>2).
__global__ void __launch_bounds__(256)
agg_kernel(const int* __restrict__ eidx, float* __restrict__ out) {
    int wid = threadIdx.x >> 5, lane = threadIdx.x & 31;
    int n = blockIdx.x * 8 + wid;
    int r0 = g_rowptr[n], r1 = g_rowptr[n + 1];
    int c0 = lane * 3, h = lane >> 2;
    bool is64 = (g_is64 != 0);

    float a0 = 0.f, a1 = 0.f, a2 = 0.f, z = 0.f;
    for (int j = r0; j < r1; j++) {
        int e = __ldg(g_perm + j);
        int src = is64 ? __ldg(eidx + 2 * e) : __ldg(eidx + e);
        float s = __ldg(g_score + (size_t)e * 8 + h);
        const float* vp = g_V + (size_t)src * 96 + c0;
        a0 = fmaf(__ldg(vp + 0), s, a0);
        a1 = fmaf(__ldg(vp + 1), s, a1);
        a2 = fmaf(__ldg(vp + 2), s, a2);
        z += s;
    }
    float inv = 1.0f / (z + 1e-6f);
    float* op = out + (size_t)n * 96 + c0;
    op[0] = a0 * inv; op[1] = a1 * inv; op[2] = a2 * inv;
}

// ============================ launch =======================================
extern "C" void kernel_launch(void* const* d_in, const int* in_sizes, int n_in,
                              void* d_out, int out_size) {
    const float* x    = (const float*)d_in[0];
    const int*   eidx = (const int*)  d_in[1];
    const float* ea   = (const float*)d_in[2];
    const float* Wq   = (const float*)d_in[3];
    const float* bq   = (const float*)d_in[4];
    const float* Wk   = (const float*)d_in[5];
    const float* bk   = (const float*)d_in[6];
    const float* We   = (const float*)d_in[7];
    const float* be   = (const float*)d_in[8];
    const float* Wv   = (const float*)d_in[9];
    const float* bv   = (const float*)d_in[10];
    float* out = (float*)d_out;

    cudaFuncSetAttribute(qkv_kernel,   cudaFuncAttributeMaxDynamicSharedMemorySize, SMEM_BYTES);
    cudaFuncSetAttribute(score_kernel, cudaFuncAttributeMaxDynamicSharedMemorySize, SMEM_BYTES);

    detect_idx_kernel<<<1, 32>>>(eidx);
    zero_deg_kernel<<<(NN + 255) / 256, 256>>>();
    prep_weights_kernel<<<4, 256>>>(Wq, Wk, Wv, We);
    hist_kernel<<<(NE + 255) / 256, 256>>>(eidx);
    scan_kernel<<<1, 1024>>>();
    scatter_kernel<<<(NE + 255) / 256, 256>>>(eidx);
    qkv_kernel<<<dim3((NN + 127) / 128, 3), 256, SMEM_BYTES>>>(x, bq, bk, bv);
    score_kernel<<<NE / 128, 256, SMEM_BYTES>>>(ea, eidx, be);
    agg_kernel<<<NN / 8, 256>>>(eidx, out);
}

// round 5
// speedup vs baseline: 2.0719x; 1.0007x over previous
#include <cuda_runtime.h>
#include <cuda_bf16.h>
#include <cstdint>

#define NN 50000
#define NE 800000
#define DIM 96
#define NH 8
#define HD 12

// ============================ scratch ======================================
__device__ float g_Q[NN * DIM];
__device__ float g_K[NN * DIM];
__device__ float g_V[NN * DIM];
__device__ int   g_is64;
// W^T images: [4 weights][hi/lo][96 rows (out j) x 104 cols (in k)] bf16
__device__ uint4 g_WT[4][2][1248];
// CSR
__device__ int   g_deg[NN];
__device__ int   g_rowptr[NN + 1];
__device__ int   g_off[NN];
__device__ int   g_pos[NE];        // edge -> CSR slot
__device__ int   g_srcs[NE];       // CSR-ordered src indices
__device__ float g_score[NE * NH]; // CSR-ordered scores [slot][8]

// ============================ smem layout ==================================
#define SM_A  0
#define SM_BH 51200
#define SM_BL 71168
#define SMEM_BYTES 91136
#define ASTR 100   // fp32 stride (floats)
#define BSTR 104   // bf16 stride (elements)

// ============================ helpers ======================================
__device__ __forceinline__ uint32_t smem_u32(const void* p) {
    uint32_t a;
    asm("{ .reg .u64 t; cvta.to.shared.u64 t, %1; cvt.u32.u64 %0, t; }" : "=r"(a) : "l"(p));
    return a;
}
__device__ __forceinline__ void cp16(uint32_t s, const void* g) {
    asm volatile("cp.async.ca.shared.global [%0], [%1], 16;" :: "r"(s), "l"(g));
}
#define CP_COMMIT_WAIT() do { \
    asm volatile("cp.async.commit_group;"); \
    asm volatile("cp.async.wait_group 0;" ::: "memory"); } while (0)

__device__ __forceinline__ void mma_bf16(float c[4], uint32_t a0, uint32_t a1,
                                         uint32_t a2, uint32_t a3,
                                         uint32_t b0, uint32_t b1) {
    asm volatile(
        "mma.sync.aligned.m16n8k16.row.col.f32.bf16.bf16.f32 "
        "{%0,%1,%2,%3}, {%4,%5,%6,%7}, {%8,%9}, {%0,%1,%2,%3};"
        : "+f"(c[0]), "+f"(c[1]), "+f"(c[2]), "+f"(c[3])
        : "r"(a0), "r"(a1), "r"(a2), "r"(a3), "r"(b0), "r"(b1));
}

__device__ __forceinline__ void split2(float2 f, uint32_t& hi, uint32_t& lo) {
    __nv_bfloat16 h0 = __float2bfloat16(f.x), h1 = __float2bfloat16(f.y);
    __nv_bfloat16 l0 = __float2bfloat16(f.x - __bfloat162float(h0));
    __nv_bfloat16 l1 = __float2bfloat16(f.y - __bfloat162float(h1));
    hi = (uint32_t)__bfloat16_as_ushort(h0) | ((uint32_t)__bfloat16_as_ushort(h1) << 16);
    lo = (uint32_t)__bfloat16_as_ushort(l0) | ((uint32_t)__bfloat16_as_ushort(l1) << 16);
}

// Warp GEMM: C[16][96] = A[r0..r0+15][0..95] (fp32 smem) @ W^T, 3-term bf16 comp.
__device__ __forceinline__ void warp_gemm(const float* As, const char* smem,
                                          int r0, int lane, float acc[12][4]) {
#pragma unroll
    for (int n = 0; n < 12; n++)
#pragma unroll
        for (int i = 0; i < 4; i++) acc[n][i] = 0.f;

    const int ar = r0 + (lane >> 2);
    const int kc = (lane & 3) * 2;
    const int br = lane >> 2;
    const __nv_bfloat16* Bh = (const __nv_bfloat16*)(smem + SM_BH);
    const __nv_bfloat16* Bl = (const __nv_bfloat16*)(smem + SM_BL);

#pragma unroll
    for (int ks = 0; ks < 6; ks++) {
        int k0 = ks * 16;
        float2 f0 = *(const float2*)(As + (size_t)ar * ASTR + k0 + kc);
        float2 f1 = *(const float2*)(As + (size_t)(ar + 8) * ASTR + k0 + kc);
        float2 f2 = *(const float2*)(As + (size_t)ar * ASTR + k0 + kc + 8);
        float2 f3 = *(const float2*)(As + (size_t)(ar + 8) * ASTR + k0 + kc + 8);
        uint32_t ah0, ah1, ah2, ah3, al0, al1, al2, al3;
        split2(f0, ah0, al0); split2(f1, ah1, al1);
        split2(f2, ah2, al2); split2(f3, ah3, al3);
#pragma unroll
        for (int n = 0; n < 12; n++) {
            const __nv_bfloat16* bh = Bh + (size_t)(n * 8 + br) * BSTR + k0 + kc;
            const __nv_bfloat16* bl = Bl + (size_t)(n * 8 + br) * BSTR + k0 + kc;
            uint32_t b0 = *(const uint32_t*)(bh);
            uint32_t b1 = *(const uint32_t*)(bh + 8);
            uint32_t c0 = *(const uint32_t*)(bl);
            uint32_t c1 = *(const uint32_t*)(bl + 8);
            mma_bf16(acc[n], ah0, ah1, ah2, ah3, b0, b1);
            mma_bf16(acc[n], al0, al1, al2, al3, b0, b1);
            mma_bf16(acc[n], ah0, ah1, ah2, ah3, c0, c1);
        }
    }
}

// =========================== small kernels =================================
__global__ void detect_idx_kernel(const int* __restrict__ eidx) {
    if (threadIdx.x == 0) {
        int acc = 0;
        for (int i = 0; i < 256; i++) acc |= eidx[2 * i + 1];
        g_is64 = (acc == 0) ? 1 : 0;
    }
}

// prep W^T images; also zero g_deg (4 blocks x 12500 each)
__global__ void prep_weights_kernel(const float* __restrict__ Wq, const float* __restrict__ Wk,
                                    const float* __restrict__ Wv, const float* __restrict__ We) {
    const float* W = (blockIdx.x == 0) ? Wq : (blockIdx.x == 1) ? Wk
                   : (blockIdx.x == 2) ? Wv : We;
    unsigned short* hi = (unsigned short*)g_WT[blockIdx.x][0];
    unsigned short* lo = (unsigned short*)g_WT[blockIdx.x][1];
    int zb = blockIdx.x * 12500;
    for (int i = threadIdx.x; i < 12500; i += blockDim.x) g_deg[zb + i] = 0;
    for (int i = threadIdx.x; i < 96 * BSTR; i += blockDim.x) { hi[i] = 0; lo[i] = 0; }
    __syncthreads();
    for (int i = threadIdx.x; i < 96 * 96; i += blockDim.x) {
        int k = i / 96, j = i - k * 96;          // W[k][j] -> WT[j][k]
        float v = W[i];
        __nv_bfloat16 h = __float2bfloat16(v);
        __nv_bfloat16 l = __float2bfloat16(v - __bfloat162float(h));
        hi[j * BSTR + k] = __bfloat16_as_ushort(h);
        lo[j * BSTR + k] = __bfloat16_as_ushort(l);
    }
}

__global__ void hist_kernel(const int* __restrict__ eidx) {
    int e = blockIdx.x * blockDim.x + threadIdx.x;
    if (e < NE) {
        int dst = g_is64 ? __ldg(eidx + 2 * (NE + e)) : __ldg(eidx + NE + e);
        atomicAdd(&g_deg[dst], 1);
    }
}

// single-block exclusive scan over g_deg -> g_rowptr, g_off
__global__ void scan_kernel() {
    const int PER = 49;
    int tid = threadIdx.x;
    int base = tid * PER;
    int sum = 0;
    for (int i = 0; i < PER; i++) {
        int idx = base + i;
        if (idx < NN) sum += g_deg[idx];
    }
    __shared__ int wsum[32];
    int lane = tid & 31, w = tid >> 5;
    int v = sum;
#pragma unroll
    for (int o = 1; o < 32; o <<= 1) {
        int t = __shfl_up_sync(0xFFFFFFFFu, v, o);
        if (lane >= o) v += t;
    }
    if (lane == 31) wsum[w] = v;
    __syncthreads();
    if (w == 0) {
        int s = wsum[lane];
#pragma unroll
        for (int o = 1; o < 32; o <<= 1) {
            int t = __shfl_up_sync(0xFFFFFFFFu, s, o);
            if (lane >= o) s += t;
        }
        wsum[lane] = s;
    }
    __syncthreads();
    int excl = v - sum + (w > 0 ? wsum[w - 1] : 0);
    int run = excl;
    for (int i = 0; i < PER; i++) {
        int idx = base + i;
        if (idx < NN) {
            g_rowptr[idx] = run;
            g_off[idx] = run;
            run += g_deg[idx];
        }
    }
    if (tid == 1023) g_rowptr[NN] = NE;
}

// scatter: also record edge->slot and CSR-ordered src
__global__ void scatter_kernel(const int* __restrict__ eidx) {
    int e = blockIdx.x * blockDim.x + threadIdx.x;
    if (e < NE) {
        int src, dst;
        if (g_is64) { src = __ldg(eidx + 2 * e); dst = __ldg(eidx + 2 * (NE + e)); }
        else        { src = __ldg(eidx + e);     dst = __ldg(eidx + NE + e); }
        int pos = atomicAdd(&g_off[dst], 1);
        g_pos[e] = pos;
        g_srcs[pos] = src;
    }
}

// ============================ QKV kernel ===================================
__global__ void __launch_bounds__(256, 2)
qkv_kernel(const float* __restrict__ x,
           const float* __restrict__ bq, const float* __restrict__ bk,
           const float* __restrict__ bv) {
    extern __shared__ __align__(16) char smem[];
    uint32_t sb = smem_u32(smem);
    int tid = threadIdx.x, wid = tid >> 5, lane = tid & 31;
    int w = blockIdx.y;
    const float* bias = (w == 0) ? bq : (w == 1) ? bk : bv;
    float* out = (w == 0) ? g_Q : (w == 1) ? g_K : g_V;

    {
        const uint4* sh = g_WT[w][0];
        const uint4* sl = g_WT[w][1];
        for (int i = tid; i < 1248; i += 256) {
            cp16(sb + SM_BH + i * 16, sh + i);
            cp16(sb + SM_BL + i * 16, sl + i);
        }
    }
    int row0 = blockIdx.x * 128;
    for (int i = tid; i < 3072; i += 256) {
        int r = i / 24, q = i - r * 24;
        int n = row0 + r;
        if (n < NN)
            cp16(sb + SM_A + (uint32_t)(r * ASTR + q * 4) * 4, x + (size_t)n * 96 + q * 4);
    }
    CP_COMMIT_WAIT();
    __syncthreads();

    float acc[12][4];
    warp_gemm((const float*)smem, smem, wid * 16, lane, acc);

    int rl = row0 + wid * 16 + (lane >> 2);
    int cb = (lane & 3) * 2;
#pragma unroll
    for (int n = 0; n < 12; n++) {
        int col = n * 8 + cb;
        float b0 = __ldg(bias + col), b1 = __ldg(bias + col + 1);
        if (rl < NN)
            *(float2*)(out + (size_t)rl * 96 + col) = make_float2(acc[n][0] + b0, acc[n][1] + b1);
        if (rl + 8 < NN)
            *(float2*)(out + (size_t)(rl + 8) * 96 + col) = make_float2(acc[n][2] + b0, acc[n][3] + b1);
    }
}

// ============================ Score kernel =================================
__global__ void __launch_bounds__(256, 2)
score_kernel(const float* __restrict__ edge_attr, const int* __restrict__ eidx,
             const float* __restrict__ be) {
    extern __shared__ __align__(16) char smem[];
    uint32_t sb = smem_u32(smem);
    int tid = threadIdx.x, wid = tid >> 5, lane = tid & 31;
    int e0 = blockIdx.x * 128;

    // early: this thread's edge indices + CSR slot (in flight under the GEMM)
    int el = tid >> 1;
    int half = tid & 1;
    int e = e0 + el;
    int src, dst;
    if (g_is64) { src = __ldg(eidx + 2 * e); dst = __ldg(eidx + 2 * (NE + e)); }
    else        { src = __ldg(eidx + e);     dst = __ldg(eidx + NE + e); }
    int pos = __ldg(g_pos + e);

    {
        const uint4* sh = g_WT[3][0];
        const uint4* sl = g_WT[3][1];
        for (int i = tid; i < 1248; i += 256) {
            cp16(sb + SM_BH + i * 16, sh + i);
            cp16(sb + SM_BL + i * 16, sl + i);
        }
    }
    for (int i = tid; i < 3072; i += 256) {
        int r = i / 24, q = i - r * 24;
        cp16(sb + SM_A + (uint32_t)(r * ASTR + q * 4) * 4,
             edge_attr + (size_t)(e0 + r) * 96 + q * 4);
    }
    CP_COMMIT_WAIT();
    __syncthreads();

    float acc[12][4];
    warp_gemm((const float*)smem, smem, wid * 16, lane, acc);
    __syncthreads();

    float* E = (float*)smem;
    {
        int rl = wid * 16 + (lane >> 2);
        int cb = (lane & 3) * 2;
#pragma unroll
        for (int n = 0; n < 12; n++) {
            int col = n * 8 + cb;
            float b0 = __ldg(be + col), b1 = __ldg(be + col + 1);
            *(float2*)(E + (size_t)rl * ASTR + col) = make_float2(acc[n][0] + b0, acc[n][1] + b1);
            *(float2*)(E + (size_t)(rl + 8) * ASTR + col) = make_float2(acc[n][2] + b0, acc[n][3] + b1);
        }
    }
    __syncthreads();

    float ev[48];
    {
        const float4* Ep = (const float4*)(E + (size_t)el * ASTR + half * 48);
#pragma unroll
        for (int i = 0; i < 12; i++) {
            float4 t = Ep[i];
            ev[i * 4 + 0] = t.x; ev[i * 4 + 1] = t.y; ev[i * 4 + 2] = t.z; ev[i * 4 + 3] = t.w;
        }
    }
    int hb = half * 4;
    const float4* Kp = (const float4*)(g_K + (size_t)src * 96 + hb * 12);
    const float4* Qp = (const float4*)(g_Q + (size_t)dst * 96 + hb * 12);
    const float inv_sqrt_d = 0.28867513459481287f;

    float sc[4];
#pragma unroll
    for (int h = 0; h < 4; h++) {
        float s = 0.f;
#pragma unroll
        for (int j = 0; j < 3; j++) {
            float4 kv = __ldg(Kp + h * 3 + j);
            float4 qv = __ldg(Qp + h * 3 + j);
            s += (kv.x * qv.x) * ev[h * 12 + j * 4 + 0];
            s += (kv.y * qv.y) * ev[h * 12 + j * 4 + 1];
            s += (kv.z * qv.z) * ev[h * 12 + j * 4 + 2];
            s += (kv.w * qv.w) * ev[h * 12 + j * 4 + 3];
        }
        s *= inv_sqrt_d;
        s = fminf(5.0f, fmaxf(-5.0f, s));
        sc[h] = __expf(s);
    }
    *(float4*)(g_score + (size_t)pos * 8 + hb) = make_float4(sc[0], sc[1], sc[2], sc[3]);
}

// ============================ Aggregate ====================================
// One warp per dst node. Thread t owns cols 3t..3t+2 (head h = t>>2).
// srcs and scores are CSR-ordered -> coalesced streaming reads; V random rows.
__global__ void __launch_bounds__(256)
agg_kernel(float* __restrict__ out) {
    int wid = threadIdx.x >> 5, lane = threadIdx.x & 31;
    int n = blockIdx.x * 8 + wid;
    int r0 = g_rowptr[n], r1 = g_rowptr[n + 1];
    int c0 = lane * 3, h = lane >> 2;

    float a0 = 0.f, a1 = 0.f, a2 = 0.f, z = 0.f;
    int j = r0;
    for (; j + 4 <= r1; j += 4) {
        int s0 = __ldg(g_srcs + j + 0), s1 = __ldg(g_srcs + j + 1);
        int s2 = __ldg(g_srcs + j + 2), s3 = __ldg(g_srcs + j + 3);
        float w0 = __ldg(g_score + (size_t)(j + 0) * 8 + h);
        float w1 = __ldg(g_score + (size_t)(j + 1) * 8 + h);
        float w2 = __ldg(g_score + (size_t)(j + 2) * 8 + h);
        float w3 = __ldg(g_score + (size_t)(j + 3) * 8 + h);
        const float* v0 = g_V + (size_t)s0 * 96 + c0;
        const float* v1 = g_V + (size_t)s1 * 96 + c0;
        const float* v2 = g_V + (size_t)s2 * 96 + c0;
        const float* v3 = g_V + (size_t)s3 * 96 + c0;
        float x00 = __ldg(v0 + 0), x01 = __ldg(v0 + 1), x02 = __ldg(v0 + 2);
        float x10 = __ldg(v1 + 0), x11 = __ldg(v1 + 1), x12 = __ldg(v1 + 2);
        float x20 = __ldg(v2 + 0), x21 = __ldg(v2 + 1), x22 = __ldg(v2 + 2);
        float x30 = __ldg(v3 + 0), x31 = __ldg(v3 + 1), x32 = __ldg(v3 + 2);
        a0 = fmaf(x00, w0, a0); a1 = fmaf(x01, w0, a1); a2 = fmaf(x02, w0, a2); z += w0;
        a0 = fmaf(x10, w1, a0); a1 = fmaf(x11, w1, a1); a2 = fmaf(x12, w1, a2); z += w1;
        a0 = fmaf(x20, w2, a0); a1 = fmaf(x21, w2, a1); a2 = fmaf(x22, w2, a2); z += w2;
        a0 = fmaf(x30, w3, a0); a1 = fmaf(x31, w3, a1); a2 = fmaf(x32, w3, a2); z += w3;
    }
    for (; j < r1; j++) {
        int s = __ldg(g_srcs + j);
        float w = __ldg(g_score + (size_t)j * 8 + h);
        const float* vp = g_V + (size_t)s * 96 + c0;
        a0 = fmaf(__ldg(vp + 0), w, a0);
        a1 = fmaf(__ldg(vp + 1), w, a1);
        a2 = fmaf(__ldg(vp + 2), w, a2);
        z += w;
    }
    float inv = 1.0f / (z + 1e-6f);
    float* op = out + (size_t)n * 96 + c0;
    op[0] = a0 * inv; op[1] = a1 * inv; op[2] = a2 * inv;
}

// ============================ launch =======================================
extern "C" void kernel_launch(void* const* d_in, const int* in_sizes, int n_in,
                              void* d_out, int out_size) {
    const float* x    = (const float*)d_in[0];
    const int*   eidx = (const int*)  d_in[1];
    const float* ea   = (const float*)d_in[2];
    const float* Wq   = (const float*)d_in[3];
    const float* bq   = (const float*)d_in[4];
    const float* Wk   = (const float*)d_in[5];
    const float* bk   = (const float*)d_in[6];
    const float* We   = (const float*)d_in[7];
    const float* be   = (const float*)d_in[8];
    const float* Wv   = (const float*)d_in[9];
    const float* bv   = (const float*)d_in[10];
    float* out = (float*)d_out;

    cudaFuncSetAttribute(qkv_kernel,   cudaFuncAttributeMaxDynamicSharedMemorySize, SMEM_BYTES);
    cudaFuncSetAttribute(score_kernel, cudaFuncAttributeMaxDynamicSharedMemorySize, SMEM_BYTES);

    detect_idx_kernel<<<1, 32>>>(eidx);
    prep_weights_kernel<<<4, 256>>>(Wq, Wk, Wv, We);
    hist_kernel<<<(NE + 255) / 256, 256>>>(eidx);
    scan_kernel<<<1, 1024>>>();
    scatter_kernel<<<(NE + 255) / 256, 256>>>(eidx);
    qkv_kernel<<<dim3((NN + 127) / 128, 3), 256, SMEM_BYTES>>>(x, bq, bk, bv);
    score_kernel<<<NE / 128, 256, SMEM_BYTES>>>(ea, eidx, be);
    agg_kernel<<<NN / 8, 256>>>(out);
}

// round 6
// speedup vs baseline: 2.4185x; 1.1673x over previous
#include <cuda_runtime.h>
#include <cuda_bf16.h>
#include <cstdint>

#define NN 50000
#define NE 800000
#define DIM 96
#define NH 8
#define HD 12

// ============================ scratch ======================================
__device__ float g_Q[NN * DIM];
__device__ float g_K[NN * DIM];
__device__ float g_V[NN * DIM];
__device__ int   g_is64;
// W^T images: [4 weights][hi/lo][96 rows (out j) x 104 cols (in k)] bf16
__device__ uint4 g_WT[4][2][1248];
// CSR
__device__ int   g_deg[NN];
__device__ int   g_rowptr[NN + 1];
__device__ int   g_off[NN];
__device__ int   g_pos[NE];        // edge -> CSR slot
__device__ int   g_srcs[NE];       // CSR-ordered src indices
__device__ float g_score[NE * NH]; // CSR-ordered scores [slot][8]
// scan temporaries
__device__ int   g_tmp[NN];
__device__ int   g_bsum[256];
__device__ int   g_boff[256];

// ============================ smem layout ==================================
#define SM_A  0
#define SM_BH 51200
#define SM_BL 71168
#define SMEM_BYTES 91136
#define ASTR 100   // fp32 stride (floats)
#define BSTR 104   // bf16 stride (elements)

#define STILES 5   // tiles per score block  (6250 = 1250*5)
#define QTILES 4   // tiles per qkv block    (392 = 98*4, guarded)

// ============================ helpers ======================================
__device__ __forceinline__ uint32_t smem_u32(const void* p) {
    uint32_t a;
    asm("{ .reg .u64 t; cvta.to.shared.u64 t, %1; cvt.u32.u64 %0, t; }" : "=r"(a) : "l"(p));
    return a;
}
__device__ __forceinline__ void cp16(uint32_t s, const void* g) {
    asm volatile("cp.async.ca.shared.global [%0], [%1], 16;" :: "r"(s), "l"(g));
}
#define CP_COMMIT() asm volatile("cp.async.commit_group;")
#define CP_WAIT0()  asm volatile("cp.async.wait_group 0;" ::: "memory")

__device__ __forceinline__ void mma_bf16(float c[4], uint32_t a0, uint32_t a1,
                                         uint32_t a2, uint32_t a3,
                                         uint32_t b0, uint32_t b1) {
    asm volatile(
        "mma.sync.aligned.m16n8k16.row.col.f32.bf16.bf16.f32 "
        "{%0,%1,%2,%3}, {%4,%5,%6,%7}, {%8,%9}, {%0,%1,%2,%3};"
        : "+f"(c[0]), "+f"(c[1]), "+f"(c[2]), "+f"(c[3])
        : "r"(a0), "r"(a1), "r"(a2), "r"(a3), "r"(b0), "r"(b1));
}

__device__ __forceinline__ void split2(float2 f, uint32_t& hi, uint32_t& lo) {
    __nv_bfloat16 h0 = __float2bfloat16(f.x), h1 = __float2bfloat16(f.y);
    __nv_bfloat16 l0 = __float2bfloat16(f.x - __bfloat162float(h0));
    __nv_bfloat16 l1 = __float2bfloat16(f.y - __bfloat162float(h1));
    hi = (uint32_t)__bfloat16_as_ushort(h0) | ((uint32_t)__bfloat16_as_ushort(h1) << 16);
    lo = (uint32_t)__bfloat16_as_ushort(l0) | ((uint32_t)__bfloat16_as_ushort(l1) << 16);
}

// Warp GEMM: C[16][96] = A[r0..r0+15][0..95] (fp32 smem) @ W^T, 3-term bf16 comp.
__device__ __forceinline__ void warp_gemm(const float* As, const char* smem,
                                          int r0, int lane, float acc[12][4]) {
#pragma unroll
    for (int n = 0; n < 12; n++)
#pragma unroll
        for (int i = 0; i < 4; i++) acc[n][i] = 0.f;

    const int ar = r0 + (lane >> 2);
    const int kc = (lane & 3) * 2;
    const int br = lane >> 2;
    const __nv_bfloat16* Bh = (const __nv_bfloat16*)(smem + SM_BH);
    const __nv_bfloat16* Bl = (const __nv_bfloat16*)(smem + SM_BL);

#pragma unroll
    for (int ks = 0; ks < 6; ks++) {
        int k0 = ks * 16;
        float2 f0 = *(const float2*)(As + (size_t)ar * ASTR + k0 + kc);
        float2 f1 = *(const float2*)(As + (size_t)(ar + 8) * ASTR + k0 + kc);
        float2 f2 = *(const float2*)(As + (size_t)ar * ASTR + k0 + kc + 8);
        float2 f3 = *(const float2*)(As + (size_t)(ar + 8) * ASTR + k0 + kc + 8);
        uint32_t ah0, ah1, ah2, ah3, al0, al1, al2, al3;
        split2(f0, ah0, al0); split2(f1, ah1, al1);
        split2(f2, ah2, al2); split2(f3, ah3, al3);
#pragma unroll
        for (int n = 0; n < 12; n++) {
            const __nv_bfloat16* bh = Bh + (size_t)(n * 8 + br) * BSTR + k0 + kc;
            const __nv_bfloat16* bl = Bl + (size_t)(n * 8 + br) * BSTR + k0 + kc;
            uint32_t b0 = *(const uint32_t*)(bh);
            uint32_t b1 = *(const uint32_t*)(bh + 8);
            uint32_t c0 = *(const uint32_t*)(bl);
            uint32_t c1 = *(const uint32_t*)(bl + 8);
            mma_bf16(acc[n], ah0, ah1, ah2, ah3, b0, b1);
            mma_bf16(acc[n], al0, al1, al2, al3, b0, b1);
            mma_bf16(acc[n], ah0, ah1, ah2, ah3, c0, c1);
        }
    }
}

// =========================== small kernels =================================
__global__ void detect_idx_kernel(const int* __restrict__ eidx) {
    if (threadIdx.x == 0) {
        int acc = 0;
        for (int i = 0; i < 256; i++) acc |= eidx[2 * i + 1];
        g_is64 = (acc == 0) ? 1 : 0;
    }
}

// prep W^T images; also zero g_deg (4 blocks x 12500 each)
__global__ void prep_weights_kernel(const float* __restrict__ Wq, const float* __restrict__ Wk,
                                    const float* __restrict__ Wv, const float* __restrict__ We) {
    const float* W = (blockIdx.x == 0) ? Wq : (blockIdx.x == 1) ? Wk
                   : (blockIdx.x == 2) ? Wv : We;
    unsigned short* hi = (unsigned short*)g_WT[blockIdx.x][0];
    unsigned short* lo = (unsigned short*)g_WT[blockIdx.x][1];
    int zb = blockIdx.x * 12500;
    for (int i = threadIdx.x; i < 12500; i += blockDim.x) g_deg[zb + i] = 0;
    for (int i = threadIdx.x; i < 96 * BSTR; i += blockDim.x) { hi[i] = 0; lo[i] = 0; }
    __syncthreads();
    for (int i = threadIdx.x; i < 96 * 96; i += blockDim.x) {
        int k = i / 96, j = i - k * 96;          // W[k][j] -> WT[j][k]
        float v = W[i];
        __nv_bfloat16 h = __float2bfloat16(v);
        __nv_bfloat16 l = __float2bfloat16(v - __bfloat162float(h));
        hi[j * BSTR + k] = __bfloat16_as_ushort(h);
        lo[j * BSTR + k] = __bfloat16_as_ushort(l);
    }
}

__global__ void hist_kernel(const int* __restrict__ eidx) {
    int e = blockIdx.x * blockDim.x + threadIdx.x;
    if (e < NE) {
        int dst = g_is64 ? __ldg(eidx + 2 * (NE + e)) : __ldg(eidx + NE + e);
        atomicAdd(&g_deg[dst], 1);
    }
}

// -------- 3-phase parallel scan --------
// phase 1: per-block (256 elems) exclusive scan -> g_tmp, block sums -> g_bsum
__global__ void scan1_kernel() {
    int tid = threadIdx.x;
    int i = blockIdx.x * 256 + tid;
    int v = (i < NN) ? g_deg[i] : 0;
    int lane = tid & 31, w = tid >> 5;
    int x = v;
#pragma unroll
    for (int o = 1; o < 32; o <<= 1) {
        int t = __shfl_up_sync(0xFFFFFFFFu, x, o);
        if (lane >= o) x += t;
    }
    __shared__ int ws[8];
    if (lane == 31) ws[w] = x;
    __syncthreads();
    if (w == 0) {
        int s = (lane < 8) ? ws[lane] : 0;
#pragma unroll
        for (int o = 1; o < 8; o <<= 1) {
            int t = __shfl_up_sync(0xFFFFFFFFu, s, o);
            if (lane >= o) s += t;
        }
        if (lane < 8) ws[lane] = s;
    }
    __syncthreads();
    int excl = x - v + (w > 0 ? ws[w - 1] : 0);
    if (i < NN) g_tmp[i] = excl;
    if (tid == 255) g_bsum[blockIdx.x] = excl + v;
}

// phase 2: scan the 196 block sums (single 256-thread block)
__global__ void scan2_kernel() {
    int tid = threadIdx.x;
    int v = (tid < 196) ? g_bsum[tid] : 0;
    int lane = tid & 31, w = tid >> 5;
    int x = v;
#pragma unroll
    for (int o = 1; o < 32; o <<= 1) {
        int t = __shfl_up_sync(0xFFFFFFFFu, x, o);
        if (lane >= o) x += t;
    }
    __shared__ int ws[8];
    if (lane == 31) ws[w] = x;
    __syncthreads();
    if (w == 0) {
        int s = (lane < 8) ? ws[lane] : 0;
#pragma unroll
        for (int o = 1; o < 8; o <<= 1) {
            int t = __shfl_up_sync(0xFFFFFFFFu, s, o);
            if (lane >= o) s += t;
        }
        if (lane < 8) ws[lane] = s;
    }
    __syncthreads();
    int excl = x - v + (w > 0 ? ws[w - 1] : 0);
    if (tid < 196) g_boff[tid] = excl;
}

// phase 3: add block offsets -> g_rowptr, g_off
__global__ void scan3_kernel() {
    int i = blockIdx.x * 256 + threadIdx.x;
    if (i < NN) {
        int r = g_tmp[i] + g_boff[blockIdx.x];
        g_rowptr[i] = r;
        g_off[i] = r;
    }
    if (i == 0) g_rowptr[NN] = NE;
}

// scatter: record edge->slot and CSR-ordered src
__global__ void scatter_kernel(const int* __restrict__ eidx) {
    int e = blockIdx.x * blockDim.x + threadIdx.x;
    if (e < NE) {
        int src, dst;
        if (g_is64) { src = __ldg(eidx + 2 * e); dst = __ldg(eidx + 2 * (NE + e)); }
        else        { src = __ldg(eidx + e);     dst = __ldg(eidx + NE + e); }
        int pos = atomicAdd(&g_off[dst], 1);
        g_pos[e] = pos;
        g_srcs[pos] = src;
    }
}

// ============================ QKV kernel ===================================
// grid (98, 3): each block does QTILES tiles of 128 rows with W resident.
__global__ void __launch_bounds__(256, 2)
qkv_kernel(const float* __restrict__ x,
           const float* __restrict__ bq, const float* __restrict__ bk,
           const float* __restrict__ bv) {
    extern __shared__ __align__(16) char smem[];
    uint32_t sb = smem_u32(smem);
    int tid = threadIdx.x, wid = tid >> 5, lane = tid & 31;
    int w = blockIdx.y;
    const float* bias = (w == 0) ? bq : (w == 1) ? bk : bv;
    float* out = (w == 0) ? g_Q : (w == 1) ? g_K : g_V;

    {
        const uint4* sh = g_WT[w][0];
        const uint4* sl = g_WT[w][1];
        for (int i = tid; i < 1248; i += 256) {
            cp16(sb + SM_BH + i * 16, sh + i);
            cp16(sb + SM_BL + i * 16, sl + i);
        }
    }
    int tile0 = blockIdx.x * QTILES;
    // first A tile
    {
        int row0 = tile0 * 128;
        for (int i = tid; i < 3072; i += 256) {
            int r = i / 24, q = i - r * 24;
            int n = row0 + r;
            if (n < NN)
                cp16(sb + SM_A + (uint32_t)(r * ASTR + q * 4) * 4, x + (size_t)n * 96 + q * 4);
        }
    }
    CP_COMMIT();

    for (int t = 0; t < QTILES; t++) {
        int row0 = (tile0 + t) * 128;
        if (row0 >= NN) break;
        CP_WAIT0();
        __syncthreads();

        float acc[12][4];
        warp_gemm((const float*)smem, smem, wid * 16, lane, acc);
        __syncthreads();   // done reading A before prefetch overwrites

        if (t + 1 < QTILES) {
            int nrow0 = (tile0 + t + 1) * 128;
            if (nrow0 < NN) {
                for (int i = tid; i < 3072; i += 256) {
                    int r = i / 24, q = i - r * 24;
                    int n = nrow0 + r;
                    if (n < NN)
                        cp16(sb + SM_A + (uint32_t)(r * ASTR + q * 4) * 4,
                             x + (size_t)n * 96 + q * 4);
                }
            }
            CP_COMMIT();
        }

        int rl = row0 + wid * 16 + (lane >> 2);
        int cb = (lane & 3) * 2;
#pragma unroll
        for (int n = 0; n < 12; n++) {
            int col = n * 8 + cb;
            float b0 = __ldg(bias + col), b1 = __ldg(bias + col + 1);
            if (rl < NN)
                *(float2*)(out + (size_t)rl * 96 + col) = make_float2(acc[n][0] + b0, acc[n][1] + b1);
            if (rl + 8 < NN)
                *(float2*)(out + (size_t)(rl + 8) * 96 + col) = make_float2(acc[n][2] + b0, acc[n][3] + b1);
        }
    }
}

// ============================ Score kernel =================================
// grid 1250: each block does STILES tiles of 128 edges with W resident.
// Pipeline: next A cp.async issued after E-reads, completes under gathers/exp.
__global__ void __launch_bounds__(256, 2)
score_kernel(const float* __restrict__ edge_attr, const int* __restrict__ eidx,
             const float* __restrict__ be) {
    extern __shared__ __align__(16) char smem[];
    uint32_t sb = smem_u32(smem);
    int tid = threadIdx.x, wid = tid >> 5, lane = tid & 31;
    int el = tid >> 1;
    int half = tid & 1;
    int hb = half * 4;
    bool is64 = (g_is64 != 0);

    {
        const uint4* sh = g_WT[3][0];
        const uint4* sl = g_WT[3][1];
        for (int i = tid; i < 1248; i += 256) {
            cp16(sb + SM_BH + i * 16, sh + i);
            cp16(sb + SM_BL + i * 16, sl + i);
        }
    }
    int tile0 = blockIdx.x * STILES;
    {
        int e0 = tile0 * 128;
        for (int i = tid; i < 3072; i += 256) {
            int r = i / 24, q = i - r * 24;
            cp16(sb + SM_A + (uint32_t)(r * ASTR + q * 4) * 4,
                 edge_attr + (size_t)(e0 + r) * 96 + q * 4);
        }
    }
    CP_COMMIT();

    for (int t = 0; t < STILES; t++) {
        int e0 = (tile0 + t) * 128;
        int e = e0 + el;
        // index loads in flight under the wait + GEMM
        int src, dst;
        if (is64) { src = __ldg(eidx + 2 * e); dst = __ldg(eidx + 2 * (NE + e)); }
        else      { src = __ldg(eidx + e);     dst = __ldg(eidx + NE + e); }
        int pos = __ldg(g_pos + e);

        CP_WAIT0();
        __syncthreads();

        float acc[12][4];
        warp_gemm((const float*)smem, smem, wid * 16, lane, acc);
        __syncthreads();

        float* E = (float*)smem;
        {
            int rl = wid * 16 + (lane >> 2);
            int cb = (lane & 3) * 2;
#pragma unroll
            for (int n = 0; n < 12; n++) {
                int col = n * 8 + cb;
                float b0 = __ldg(be + col), b1 = __ldg(be + col + 1);
                *(float2*)(E + (size_t)rl * ASTR + col) = make_float2(acc[n][0] + b0, acc[n][1] + b1);
                *(float2*)(E + (size_t)(rl + 8) * ASTR + col) = make_float2(acc[n][2] + b0, acc[n][3] + b1);
            }
        }
        __syncthreads();

        float ev[48];
        {
            const float4* Ep = (const float4*)(E + (size_t)el * ASTR + half * 48);
#pragma unroll
            for (int i = 0; i < 12; i++) {
                float4 v = Ep[i];
                ev[i * 4 + 0] = v.x; ev[i * 4 + 1] = v.y; ev[i * 4 + 2] = v.z; ev[i * 4 + 3] = v.w;
            }
        }
        __syncthreads();   // all E reads done; A region free

        if (t + 1 < STILES) {  // prefetch next A under the gathers/exp below
            int ne0 = (tile0 + t + 1) * 128;
            for (int i = tid; i < 3072; i += 256) {
                int r = i / 24, q = i - r * 24;
                cp16(sb + SM_A + (uint32_t)(r * ASTR + q * 4) * 4,
                     edge_attr + (size_t)(ne0 + r) * 96 + q * 4);
            }
            CP_COMMIT();
        }

        const float4* Kp = (const float4*)(g_K + (size_t)src * 96 + hb * 12);
        const float4* Qp = (const float4*)(g_Q + (size_t)dst * 96 + hb * 12);
        const float inv_sqrt_d = 0.28867513459481287f;

        float sc[4];
#pragma unroll
        for (int h = 0; h < 4; h++) {
            float s = 0.f;
#pragma unroll
            for (int j = 0; j < 3; j++) {
                float4 kv = __ldg(Kp + h * 3 + j);
                float4 qv = __ldg(Qp + h * 3 + j);
                s += (kv.x * qv.x) * ev[h * 12 + j * 4 + 0];
                s += (kv.y * qv.y) * ev[h * 12 + j * 4 + 1];
                s += (kv.z * qv.z) * ev[h * 12 + j * 4 + 2];
                s += (kv.w * qv.w) * ev[h * 12 + j * 4 + 3];
            }
            s *= inv_sqrt_d;
            s = fminf(5.0f, fmaxf(-5.0f, s));
            sc[h] = __expf(s);
        }
        *(float4*)(g_score + (size_t)pos * 8 + hb) = make_float4(sc[0], sc[1], sc[2], sc[3]);
    }
}

// ============================ Aggregate ====================================
__global__ void __launch_bounds__(256)
agg_kernel(float* __restrict__ out) {
    int wid = threadIdx.x >> 5, lane = threadIdx.x & 31;
    int n = blockIdx.x * 8 + wid;
    int r0 = g_rowptr[n], r1 = g_rowptr[n + 1];
    int c0 = lane * 3, h = lane >> 2;

    float a0 = 0.f, a1 = 0.f, a2 = 0.f, z = 0.f;
    int j = r0;
    for (; j + 4 <= r1; j += 4) {
        int s0 = __ldg(g_srcs + j + 0), s1 = __ldg(g_srcs + j + 1);
        int s2 = __ldg(g_srcs + j + 2), s3 = __ldg(g_srcs + j + 3);
        float w0 = __ldg(g_score + (size_t)(j + 0) * 8 + h);
        float w1 = __ldg(g_score + (size_t)(j + 1) * 8 + h);
        float w2 = __ldg(g_score + (size_t)(j + 2) * 8 + h);
        float w3 = __ldg(g_score + (size_t)(j + 3) * 8 + h);
        const float* v0 = g_V + (size_t)s0 * 96 + c0;
        const float* v1 = g_V + (size_t)s1 * 96 + c0;
        const float* v2 = g_V + (size_t)s2 * 96 + c0;
        const float* v3 = g_V + (size_t)s3 * 96 + c0;
        float x00 = __ldg(v0 + 0), x01 = __ldg(v0 + 1), x02 = __ldg(v0 + 2);
        float x10 = __ldg(v1 + 0), x11 = __ldg(v1 + 1), x12 = __ldg(v1 + 2);
        float x20 = __ldg(v2 + 0), x21 = __ldg(v2 + 1), x22 = __ldg(v2 + 2);
        float x30 = __ldg(v3 + 0), x31 = __ldg(v3 + 1), x32 = __ldg(v3 + 2);
        a0 = fmaf(x00, w0, a0); a1 = fmaf(x01, w0, a1); a2 = fmaf(x02, w0, a2); z += w0;
        a0 = fmaf(x10, w1, a0); a1 = fmaf(x11, w1, a1); a2 = fmaf(x12, w1, a2); z += w1;
        a0 = fmaf(x20, w2, a0); a1 = fmaf(x21, w2, a1); a2 = fmaf(x22, w2, a2); z += w2;
        a0 = fmaf(x30, w3, a0); a1 = fmaf(x31, w3, a1); a2 = fmaf(x32, w3, a2); z += w3;
    }
    for (; j < r1; j++) {
        int s = __ldg(g_srcs + j);
        float w = __ldg(g_score + (size_t)j * 8 + h);
        const float* vp = g_V + (size_t)s * 96 + c0;
        a0 = fmaf(__ldg(vp + 0), w, a0);
        a1 = fmaf(__ldg(vp + 1), w, a1);
        a2 = fmaf(__ldg(vp + 2), w, a2);
        z += w;
    }
    float inv = 1.0f / (z + 1e-6f);
    float* op = out + (size_t)n * 96 + c0;
    op[0] = a0 * inv; op[1] = a1 * inv; op[2] = a2 * inv;
}

// ============================ launch =======================================
extern "C" void kernel_launch(void* const* d_in, const int* in_sizes, int n_in,
                              void* d_out, int out_size) {
    const float* x    = (const float*)d_in[0];
    const int*   eidx = (const int*)  d_in[1];
    const float* ea   = (const float*)d_in[2];
    const float* Wq   = (const float*)d_in[3];
    const float* bq   = (const float*)d_in[4];
    const float* Wk   = (const float*)d_in[5];
    const float* bk   = (const float*)d_in[6];
    const float* We   = (const float*)d_in[7];
    const float* be   = (const float*)d_in[8];
    const float* Wv   = (const float*)d_in[9];
    const float* bv   = (const float*)d_in[10];
    float* out = (float*)d_out;

    cudaFuncSetAttribute(qkv_kernel,   cudaFuncAttributeMaxDynamicSharedMemorySize, SMEM_BYTES);
    cudaFuncSetAttribute(score_kernel, cudaFuncAttributeMaxDynamicSharedMemorySize, SMEM_BYTES);

    detect_idx_kernel<<<1, 32>>>(eidx);
    prep_weights_kernel<<<4, 256>>>(Wq, Wk, Wv, We);
    hist_kernel<<<(NE + 255) / 256, 256>>>(eidx);
    scan1_kernel<<<196, 256>>>();
    scan2_kernel<<<1, 256>>>();
    scan3_kernel<<<196, 256>>>();
    scatter_kernel<<<(NE + 255) / 256, 256>>>(eidx);
    qkv_kernel<<<dim3(98, 3), 256, SMEM_BYTES>>>(x, bq, bk, bv);
    score_kernel<<<1250, 256, SMEM_BYTES>>>(ea, eidx, be);
    agg_kernel<<<NN / 8, 256>>>(out);
}